// round 8
// baseline (speedup 1.0000x reference)
#include <cuda_runtime.h>

// Problem-fixed shapes: B=4, C=256, Ch=128, H=W=64 -> N=4096
#define NPIX 4096

// ---------------- scratch (no allocations allowed -> __device__ global) ----
#define OFF_T  0
#define OFF_F  2097152
#define OFF_G  4194304
#define OFF_H  6291456
#define OFF_PM 10485760
#define OFF_PS 11010048
#define OFF_FM 11534336
#define OFF_FS 11550720
#define OFF_E  11567104ull                  // exp values, 4*4096*4096
#define SCRATCH_FLOATS (11567104ull + 67108864ull)

static __device__ float g_scratch[SCRATCH_FLOATS];

// ---------------------------------------------------------------------------
__device__ __forceinline__ unsigned f2tf32(float x) {
    unsigned r;
    asm("cvt.rna.tf32.f32 %0, %1;" : "=r"(r) : "f"(x));
    return r;
}

#define MMA_TF32(c, a, b)                                                    \
    asm volatile(                                                            \
        "mma.sync.aligned.m16n8k8.row.col.f32.tf32.tf32.f32 "                \
        "{%0,%1,%2,%3},{%4,%5,%6,%7},{%8,%9},{%0,%1,%2,%3};"                 \
        : "+f"(c[0]), "+f"(c[1]), "+f"(c[2]), "+f"(c[3])                     \
        : "r"(a[0]), "r"(a[1]), "r"(a[2]), "r"(a[3]), "r"(b[0]), "r"(b[1]))

// ---------------------------------------------------------------------------
// Tensor-core GEMM:  C[M x 4096] = epi( A[M x K] @ X[K x 4096] )
//   ACM=1: A is k-major (f for attn gemm).  SPLIT=3: 3xTF32.  MODE as before
//   (0 relu+bias, 1 +bias, 2 gamma*acc+residual, 3 raw).
//   STATS=1: attn gemm — also emit per-(slab,column) max into g_scratch PM.
//   BPROC=1: final gemm — B elements scaled by inv[col] while staging, and
//            blockIdx.y==0 writes the normalized value to attnWr (d_out).
// Software-pipelined: next tile's global loads staged in registers during MMA.
// ---------------------------------------------------------------------------
template <int ACM, int SPLIT, int MODE, int STATS, int BPROC>
__global__ __launch_bounds__(256)
void mma_gemm(const float* __restrict__ A, size_t aStride, int lda,
              const float* __restrict__ X, size_t xStride,
              const float* __restrict__ bias,
              const float* __restrict__ resAll,
              const float* __restrict__ gamma,
              float* __restrict__ C, size_t cStride, int K,
              float* __restrict__ attnWr)
{
    constexpr int BK = 16;
    constexpr int LDSW = 136;

    extern __shared__ float sm_[];
    float* Ah = sm_;
    float* Bh = Ah + BK * LDSW;
    float* Al = (SPLIT == 3) ? (Bh + BK * LDSW) : Ah;   // alias unused
    float* Bl = (SPLIT == 3) ? (Al + BK * LDSW) : Bh;

    __shared__ float sstat[2][128];

    const float* Ab = A + (size_t)blockIdx.z * aStride;
    const float* Xb = X + (size_t)blockIdx.z * xStride;
    float*       Cb = C + (size_t)blockIdx.z * cStride;
    const float* invB  = g_scratch + OFF_FS + (size_t)blockIdx.z * NPIX;
    float*       attnB = BPROC ? (attnWr + (size_t)blockIdx.z * (size_t)NPIX * NPIX)
                               : (float*)nullptr;

    const int m0   = blockIdx.y * 128;
    const int n0   = blockIdx.x * 128;
    const int t    = threadIdx.x;
    const int lane = t & 31;
    const int warp = t >> 5;
    const int wm   = (warp >> 2) * 64;
    const int wn   = (warp & 3) * 32;
    const int gid  = lane >> 2;
    const int tig  = lane & 3;

    // staged-load index precompute
    const int br0 = t >> 5;            // B row for i=0 (0..7); i=1 adds 8
    const int bc  = (t & 31) * 4;      // B col
    const int ar0 = br0, ac = bc;      // ACM==1 A indexes (same pattern)
    const int am  = t >> 2;            // ACM==0: A row m (0..63); i=1 adds 64
    const int ak  = (t & 3) * 4;       // ACM==0: A k-seg

    float acc[4][4][4];
#pragma unroll
    for (int mt = 0; mt < 4; mt++)
#pragma unroll
        for (int nt = 0; nt < 4; nt++)
#pragma unroll
            for (int r = 0; r < 4; r++) acc[mt][nt][r] = 0.0f;

    float4 aS[2], bS[2];

    // ---- staged global loads for tile at k0 ----
    auto loadStage = [&](int k0) {
#pragma unroll
        for (int i = 0; i < 2; i++) {
            int r = br0 + 8 * i;
            float4 v = *(const float4*)(Xb + (size_t)(k0 + r) * NPIX + n0 + bc);
            if (BPROC) {
                float4 iv = *(const float4*)(invB + n0 + bc);
                v.x *= iv.x; v.y *= iv.y; v.z *= iv.z; v.w *= iv.w;
                if (blockIdx.y == 0)
                    *(float4*)(attnB + (size_t)(k0 + r) * NPIX + n0 + bc) = v;
            }
            bS[i] = v;
        }
        if (ACM) {
#pragma unroll
            for (int i = 0; i < 2; i++) {
                int r = ar0 + 8 * i;
                aS[i] = *(const float4*)(Ab + (size_t)(k0 + r) * lda + m0 + ac);
            }
        } else {
#pragma unroll
            for (int i = 0; i < 2; i++) {
                int m = am + 64 * i;
                aS[i] = *(const float4*)(Ab + (size_t)(m0 + m) * lda + k0 + ak);
            }
        }
    };

    // ---- convert staged regs -> smem tiles ----
    auto storeStage = [&]() {
#pragma unroll
        for (int i = 0; i < 2; i++) {
            int r = br0 + 8 * i;
            float4 v = bS[i];
            float4 hv;
            hv.x = __uint_as_float(f2tf32(v.x));
            hv.y = __uint_as_float(f2tf32(v.y));
            hv.z = __uint_as_float(f2tf32(v.z));
            hv.w = __uint_as_float(f2tf32(v.w));
            *(float4*)(&Bh[r * LDSW + bc]) = hv;
            if (SPLIT == 3) {
                float4 lv;
                lv.x = __uint_as_float(f2tf32(v.x - hv.x));
                lv.y = __uint_as_float(f2tf32(v.y - hv.y));
                lv.z = __uint_as_float(f2tf32(v.z - hv.z));
                lv.w = __uint_as_float(f2tf32(v.w - hv.w));
                *(float4*)(&Bl[r * LDSW + bc]) = lv;
            }
        }
        if (ACM) {
#pragma unroll
            for (int i = 0; i < 2; i++) {
                int r = ar0 + 8 * i;
                float4 v = aS[i];
                float4 hv;
                hv.x = __uint_as_float(f2tf32(v.x));
                hv.y = __uint_as_float(f2tf32(v.y));
                hv.z = __uint_as_float(f2tf32(v.z));
                hv.w = __uint_as_float(f2tf32(v.w));
                *(float4*)(&Ah[r * LDSW + ac]) = hv;
                if (SPLIT == 3) {
                    float4 lv;
                    lv.x = __uint_as_float(f2tf32(v.x - hv.x));
                    lv.y = __uint_as_float(f2tf32(v.y - hv.y));
                    lv.z = __uint_as_float(f2tf32(v.z - hv.z));
                    lv.w = __uint_as_float(f2tf32(v.w - hv.w));
                    *(float4*)(&Al[r * LDSW + ac]) = lv;
                }
            }
        } else {
#pragma unroll
            for (int i = 0; i < 2; i++) {
                int m = am + 64 * i;
                float4 v = aS[i];
                float h0 = __uint_as_float(f2tf32(v.x));
                float h1 = __uint_as_float(f2tf32(v.y));
                float h2 = __uint_as_float(f2tf32(v.z));
                float h3 = __uint_as_float(f2tf32(v.w));
                Ah[(ak + 0) * LDSW + m] = h0;
                Ah[(ak + 1) * LDSW + m] = h1;
                Ah[(ak + 2) * LDSW + m] = h2;
                Ah[(ak + 3) * LDSW + m] = h3;
                if (SPLIT == 3) {
                    Al[(ak + 0) * LDSW + m] = __uint_as_float(f2tf32(v.x - h0));
                    Al[(ak + 1) * LDSW + m] = __uint_as_float(f2tf32(v.y - h1));
                    Al[(ak + 2) * LDSW + m] = __uint_as_float(f2tf32(v.z - h2));
                    Al[(ak + 3) * LDSW + m] = __uint_as_float(f2tf32(v.w - h3));
                }
            }
        }
    };

    loadStage(0);

    for (int k0 = 0; k0 < K; k0 += BK) {
        __syncthreads();          // previous tile's fragment reads done
        storeStage();
        if (k0 + BK < K) loadStage(k0 + BK);   // overlap with MMA below
        __syncthreads();

#pragma unroll
        for (int ks = 0; ks < BK; ks += 8) {
            unsigned bh[4][2], bl[4][2];
#pragma unroll
            for (int nt = 0; nt < 4; nt++) {
                int col = wn + nt * 8 + gid;
                bh[nt][0] = __float_as_uint(Bh[(ks + tig) * LDSW + col]);
                bh[nt][1] = __float_as_uint(Bh[(ks + 4 + tig) * LDSW + col]);
                if (SPLIT == 3) {
                    bl[nt][0] = __float_as_uint(Bl[(ks + tig) * LDSW + col]);
                    bl[nt][1] = __float_as_uint(Bl[(ks + 4 + tig) * LDSW + col]);
                }
            }
#pragma unroll
            for (int mt = 0; mt < 4; mt++) {
                int rowm = wm + mt * 16 + gid;
                unsigned ah[4], al[4];
                ah[0] = __float_as_uint(Ah[(ks + tig) * LDSW + rowm]);
                ah[1] = __float_as_uint(Ah[(ks + tig) * LDSW + rowm + 8]);
                ah[2] = __float_as_uint(Ah[(ks + 4 + tig) * LDSW + rowm]);
                ah[3] = __float_as_uint(Ah[(ks + 4 + tig) * LDSW + rowm + 8]);
                if (SPLIT == 3) {
                    al[0] = __float_as_uint(Al[(ks + tig) * LDSW + rowm]);
                    al[1] = __float_as_uint(Al[(ks + tig) * LDSW + rowm + 8]);
                    al[2] = __float_as_uint(Al[(ks + 4 + tig) * LDSW + rowm]);
                    al[3] = __float_as_uint(Al[(ks + 4 + tig) * LDSW + rowm + 8]);
                }
#pragma unroll
                for (int nt = 0; nt < 4; nt++) {
                    if (SPLIT == 3) {
                        MMA_TF32(acc[mt][nt], al, bh[nt]);
                        MMA_TF32(acc[mt][nt], ah, bl[nt]);
                    }
                    MMA_TF32(acc[mt][nt], ah, bh[nt]);
                }
            }
        }
    }

    // ---- epilogue: store ----
    const float gm = (MODE == 2) ? *gamma : 0.0f;
#pragma unroll
    for (int mt = 0; mt < 4; mt++) {
#pragma unroll
        for (int half = 0; half < 2; half++) {
            const int m = m0 + wm + mt * 16 + gid + half * 8;
            float bv = 0.0f;
            if (MODE == 0 || MODE == 1) bv = bias[m];
#pragma unroll
            for (int nt = 0; nt < 4; nt++) {
                const int col = n0 + wn + nt * 8 + tig * 2;
                float v0 = acc[mt][nt][half * 2 + 0];
                float v1 = acc[mt][nt][half * 2 + 1];
                if (MODE == 0) {
                    v0 = fmaxf(v0 + bv, 0.0f);
                    v1 = fmaxf(v1 + bv, 0.0f);
                } else if (MODE == 1) {
                    v0 += bv;
                    v1 += bv;
                } else if (MODE == 2) {
                    const float* rp = resAll + (size_t)blockIdx.z * cStride +
                                      (size_t)m * NPIX + col;
                    v0 = fmaf(gm, v0, rp[0]);
                    v1 = fmaf(gm, v1, rp[1]);
                }
                *(float2*)(Cb + (size_t)m * NPIX + col) = make_float2(v0, v1);
            }
        }
    }

    // ---- fused per-column (over n/rows) max for softmax ----
    if (STATS) {
        float cmax[8];
#pragma unroll
        for (int j = 0; j < 8; j++) cmax[j] = -3.402823466e38f;
#pragma unroll
        for (int nt = 0; nt < 4; nt++)
#pragma unroll
            for (int c = 0; c < 2; c++)
#pragma unroll
                for (int mt = 0; mt < 4; mt++)
#pragma unroll
                    for (int half = 0; half < 2; half++)
                        cmax[nt * 2 + c] = fmaxf(cmax[nt * 2 + c],
                                                 acc[mt][nt][half * 2 + c]);
#pragma unroll
        for (int j = 0; j < 8; j++) {
#pragma unroll
            for (int o = 4; o < 32; o <<= 1)
                cmax[j] = fmaxf(cmax[j], __shfl_xor_sync(0xffffffffu, cmax[j], o));
        }
        if (lane < 4) {
#pragma unroll
            for (int nt = 0; nt < 4; nt++)
#pragma unroll
                for (int c = 0; c < 2; c++)
                    sstat[warp >> 2][wn + nt * 8 + tig * 2 + c] = cmax[nt * 2 + c];
        }
        __syncthreads();
        if (t < 128) {
            const size_t pmi = OFF_PM +
                ((size_t)blockIdx.z * 32 + blockIdx.y) * NPIX + n0 + t;
            g_scratch[pmi] = fmaxf(sstat[0][t], sstat[1][t]);
        }
    }
}

// ---------------------------------------------------------------------------
__global__ void comb_max()
{
    const int m = blockIdx.x * 256 + threadIdx.x;
    const int b = blockIdx.y;
    float mx = -3.402823466e38f;
    for (int s = 0; s < 32; s++)
        mx = fmaxf(mx, g_scratch[OFF_PM + ((size_t)b * 32 + s) * NPIX + m]);
    g_scratch[OFF_FM + (size_t)b * NPIX + m] = mx;
}

// e = exp(v - max), stored to scratch E; per-slab sums to PS.
__global__ void exp_pass(const float* __restrict__ attnRaw)
{
    const int m  = blockIdx.x * 256 + threadIdx.x;
    const int b  = blockIdx.z;
    const int ns = blockIdx.y;
    const float mx = g_scratch[OFF_FM + (size_t)b * NPIX + m];
    const size_t off = (size_t)b * NPIX * NPIX + (size_t)ns * 128 * NPIX + m;
    const float* p = attnRaw + off;
    float* ep = g_scratch + OFF_E + off;
    float s = 0.0f;
#pragma unroll 4
    for (int n = 0; n < 128; n++) {
        float e = __expf(p[(size_t)n * NPIX] - mx);
        ep[(size_t)n * NPIX] = e;
        s += e;
    }
    g_scratch[OFF_PS + ((size_t)b * 32 + ns) * NPIX + m] = s;
}

__global__ void comb_sum()
{
    const int m = blockIdx.x * 256 + threadIdx.x;
    const int b = blockIdx.y;
    float s = 0.0f;
    for (int i = 0; i < 32; i++)
        s += g_scratch[OFF_PS + ((size_t)b * 32 + i) * NPIX + m];
    g_scratch[OFF_FS + (size_t)b * NPIX + m] = 1.0f / s;
}

// ---------------------------------------------------------------------------
extern "C" void kernel_launch(void* const* d_in, const int* in_sizes, int n_in,
                              void* d_out, int out_size)
{
    (void)in_sizes; (void)n_in; (void)out_size;

    const float* x     = (const float*)d_in[0];
    const float* wf1   = (const float*)d_in[1];
    const float* bf1   = (const float*)d_in[2];
    const float* wf2   = (const float*)d_in[3];
    const float* bf2   = (const float*)d_in[4];
    const float* wg1   = (const float*)d_in[5];
    const float* bg1   = (const float*)d_in[6];
    const float* wg2   = (const float*)d_in[7];
    const float* bg2   = (const float*)d_in[8];
    const float* wh    = (const float*)d_in[9];
    const float* bh    = (const float*)d_in[10];
    const float* gamma = (const float*)d_in[11];

    float* out  = (float*)d_out;                       // (B, C, H, W)
    float* attn = out + (size_t)4 * 256 * NPIX;        // (B, N, N)

    float* scratch = nullptr;
    cudaGetSymbolAddress((void**)&scratch, g_scratch);
    float* tbuf = scratch + OFF_T;
    float* fbuf = scratch + OFF_F;
    float* gbuf = scratch + OFF_G;
    float* hbuf = scratch + OFF_H;
    float* ebuf = scratch + OFF_E;

    dim3 blk(256);
    const size_t sX  = (size_t)256 * NPIX;
    const size_t sCh = (size_t)128 * NPIX;
    const size_t sAt = (size_t)NPIX * NPIX;
    const size_t smem1 = 2 * 16 * 136 * sizeof(float);   // non-split tiles
    const size_t smem3 = 4 * 16 * 136 * sizeof(float);   // split tiles

    // projections (f/g path: 3xTF32)
    mma_gemm<0, 3, 0, 0, 0><<<dim3(32, 1, 4), blk, smem3>>>(
        wf1, 0, 256, x, sX, bf1, nullptr, nullptr, tbuf, sCh, 256, nullptr);
    mma_gemm<0, 3, 1, 0, 0><<<dim3(32, 1, 4), blk, smem3>>>(
        wf2, 0, 128, tbuf, sCh, bf2, nullptr, nullptr, fbuf, sCh, 128, nullptr);
    mma_gemm<0, 3, 0, 0, 0><<<dim3(32, 1, 4), blk, smem3>>>(
        wg1, 0, 256, x, sX, bg1, nullptr, nullptr, tbuf, sCh, 256, nullptr);
    mma_gemm<0, 3, 1, 0, 0><<<dim3(32, 1, 4), blk, smem3>>>(
        wg2, 0, 128, tbuf, sCh, bg2, nullptr, nullptr, gbuf, sCh, 128, nullptr);
    mma_gemm<0, 1, 1, 0, 0><<<dim3(32, 2, 4), blk, smem1>>>(
        wh, 0, 256, x, sX, bh, nullptr, nullptr, hbuf, sX, 256, nullptr);

    // attn logits = f^T g (3xTF32) -> d_out attn region (temporary raw),
    // fused per-(slab,col) max stats into PM.
    mma_gemm<1, 3, 3, 1, 0><<<dim3(32, 32, 4), blk, smem3>>>(
        fbuf, sCh, NPIX, gbuf, sCh, nullptr, nullptr, nullptr,
        attn, sAt, 128, nullptr);

    comb_max<<<dim3(16, 4), blk>>>();
    exp_pass<<<dim3(16, 32, 4), blk>>>(attn);
    comb_sum<<<dim3(16, 4), blk>>>();

    // final: out = gamma * (h @ (e*inv)) + x ; normalized attn written to
    // d_out by blockIdx.y==0 blocks while staging B.
    mma_gemm<0, 1, 2, 0, 1><<<dim3(32, 2, 4), blk, smem1>>>(
        hbuf, sX, NPIX, ebuf, sAt, nullptr, x, gamma, out, sX, 4096, attn);
}

// round 10
// speedup vs baseline: 1.2892x; 1.2892x over previous
#include <cuda_runtime.h>
#include <cuda_bf16.h>
#include <cstdint>

// Problem-fixed shapes: B=4, C=256, Ch=128, H=W=64 -> N=4096
#define NPIX 4096

// ---------------- scratch (no allocations allowed -> __device__ global) ----
#define OFF_T  0
#define OFF_F  2097152
#define OFF_G  4194304
#define OFF_H  6291456
#define OFF_PM 10485760
#define OFF_PS 11010048
#define OFF_FM 11534336
#define OFF_FS 11550720
#define SCRATCH_FLOATS 11567104

static __device__ float g_scratch[SCRATCH_FLOATS];

// ---------------------------------------------------------------------------
__device__ __forceinline__ unsigned packbf(float x, float y) {
    __nv_bfloat162 t = __floats2bfloat162_rn(x, y);   // .x = low half
    return reinterpret_cast<unsigned&>(t);
}
__device__ __forceinline__ float bfhi(float x) {
    return __bfloat162float(__float2bfloat16(x));
}

#define MMA_BF16(c, a, b)                                                    \
    asm volatile(                                                            \
        "mma.sync.aligned.m16n8k16.row.col.f32.bf16.bf16.f32 "               \
        "{%0,%1,%2,%3},{%4,%5,%6,%7},{%8,%9},{%0,%1,%2,%3};"                 \
        : "+f"(c[0]), "+f"(c[1]), "+f"(c[2]), "+f"(c[3])                     \
        : "r"(a[0]), "r"(a[1]), "r"(a[2]), "r"(a[3]), "r"(b[0]), "r"(b[1]))

// ---------------------------------------------------------------------------
// bf16 tensor-core GEMM:  C[M x 4096] = epi( A[M x K] @ X[K x 4096] )
//   BM: 128 (256 thr) or 256 (512 thr); tile BM x 128, BK=16.
//   ACM=1: A stored k-major (f for attn gemm).
//   SPLIT=3: bf16 hi/lo 3-product compensation. SPLIT=1: single bf16.
//   MODE 0: relu(acc+bias)  1: acc+bias  2: final (B scaled by inv[col] at
//           staging + normalized writeback to eWr; out = gamma*acc + res)
//           3: raw store
//   STATS=1: emit per-(slab,col) max of C into PM (attn gemm).
// Smem: bf16 pairs as u32 words; row pitch 12 words (24 bf16) ->
// conflict-free fragment LDS.
// ---------------------------------------------------------------------------
template <int BM, int ACM, int SPLIT, int MODE, int STATS>
__global__ __launch_bounds__(BM * 2)
void mma_gemm(const float* __restrict__ A, size_t aStride, int lda,
              const float* __restrict__ X, size_t xStride,
              const float* __restrict__ bias,
              const float* __restrict__ resAll,
              const float* __restrict__ gamma,
              float* __restrict__ C, size_t cStride, int K,
              float* __restrict__ eWr)
{
    constexpr int AW = BM * 12;      // A tile words
    constexpr int BW = 128 * 12;     // B tile words
    constexpr int KPT = 1024 / BM;   // B k-rows per thread (8 or 4)

    extern __shared__ unsigned smw[];
    unsigned* Ahw = smw;
    unsigned* Bhw = smw + AW;
    unsigned* Alw = (SPLIT == 3) ? (smw + AW + BW) : smw;
    unsigned* Blw = (SPLIT == 3) ? (smw + AW + BW + AW) : smw;

    __shared__ float sstat[4][128];

    const int z = blockIdx.z;
    const float* Ab = A + (size_t)z * aStride;
    const float* Xb = X + (size_t)z * xStride;
    float*       Cb = C + (size_t)z * cStride;
    float*       eWrB = (MODE == 2) ? (eWr + (size_t)z * xStride) : (float*)nullptr;

    const int m0   = blockIdx.y * BM;
    const int n0   = blockIdx.x * 128;
    const int t    = threadIdx.x;
    const int lane = t & 31;
    const int warp = t >> 5;
    const int wm   = (warp >> 2) * 64;
    const int wn   = (warp & 3) * 32;
    const int gid  = lane >> 2;
    const int tig  = lane & 3;

    // staging maps
    const int nB   = t & 127;
    const int kbB  = (t >> 7) * KPT;
    const int mA0  = t >> 1;              // ACM0
    const int kshA = (t & 1) * 8;
    const int mA1  = t & (BM - 1);        // ACM1
    const int kbA  = (t >= BM) ? 8 : 0;

    const float inv_n = (MODE == 2)
        ? g_scratch[OFF_FS + (size_t)z * NPIX + n0 + nB] : 0.0f;

    float acc[4][4][4];
#pragma unroll
    for (int mt = 0; mt < 4; mt++)
#pragma unroll
        for (int nt = 0; nt < 4; nt++)
#pragma unroll
            for (int r = 0; r < 4; r++) acc[mt][nt][r] = 0.0f;

    float  bv[KPT];
    float  av[8];
    float4 a4[2];

    auto loadStage = [&](int k0) {
#pragma unroll
        for (int j = 0; j < KPT; j++) {
            const size_t gi = (size_t)(k0 + kbB + j) * NPIX + n0 + nB;
            float v = Xb[gi];
            if (MODE == 2) { v *= inv_n; eWrB[gi] = v; }
            bv[j] = v;
        }
        if (ACM) {
#pragma unroll
            for (int j = 0; j < 8; j++)
                av[j] = Ab[(size_t)(k0 + kbA + j) * lda + m0 + mA1];
        } else {
            a4[0] = *(const float4*)(Ab + (size_t)(m0 + mA0) * lda + k0 + kshA);
            a4[1] = *(const float4*)(Ab + (size_t)(m0 + mA0) * lda + k0 + kshA + 4);
        }
    };

    auto storeStage = [&]() {
#pragma unroll
        for (int j2 = 0; j2 < KPT / 2; j2++) {
            const float x0 = bv[2 * j2], x1 = bv[2 * j2 + 1];
            const int w = nB * 12 + kbB / 2 + j2;
            Bhw[w] = packbf(x0, x1);
            if (SPLIT == 3) Blw[w] = packbf(x0 - bfhi(x0), x1 - bfhi(x1));
        }
        if (ACM) {
#pragma unroll
            for (int j2 = 0; j2 < 4; j2++) {
                const float x0 = av[2 * j2], x1 = av[2 * j2 + 1];
                const int w = mA1 * 12 + kbA / 2 + j2;
                Ahw[w] = packbf(x0, x1);
                if (SPLIT == 3) Alw[w] = packbf(x0 - bfhi(x0), x1 - bfhi(x1));
            }
        } else {
            const int w = mA0 * 12 + kshA / 2;
            const float xs[8] = {a4[0].x, a4[0].y, a4[0].z, a4[0].w,
                                 a4[1].x, a4[1].y, a4[1].z, a4[1].w};
#pragma unroll
            for (int j2 = 0; j2 < 4; j2++) {
                const float x0 = xs[2 * j2], x1 = xs[2 * j2 + 1];
                Ahw[w + j2] = packbf(x0, x1);
                if (SPLIT == 3) Alw[w + j2] = packbf(x0 - bfhi(x0), x1 - bfhi(x1));
            }
        }
    };

    loadStage(0);

    for (int k0 = 0; k0 < K; k0 += 16) {
        __syncthreads();
        storeStage();
        if (k0 + 16 < K) loadStage(k0 + 16);
        __syncthreads();

        unsigned bhf[4][2], blf[4][2];
#pragma unroll
        for (int nt = 0; nt < 4; nt++) {
            const int nb = (wn + nt * 8 + gid) * 12 + tig;
            bhf[nt][0] = Bhw[nb];
            bhf[nt][1] = Bhw[nb + 4];
            if (SPLIT == 3) {
                blf[nt][0] = Blw[nb];
                blf[nt][1] = Blw[nb + 4];
            }
        }
#pragma unroll
        for (int mt = 0; mt < 4; mt++) {
            const int ab = (wm + mt * 16 + gid) * 12 + tig;
            unsigned ah[4], al[4];
            ah[0] = Ahw[ab];
            ah[1] = Ahw[ab + 96];
            ah[2] = Ahw[ab + 4];
            ah[3] = Ahw[ab + 100];
            if (SPLIT == 3) {
                al[0] = Alw[ab];
                al[1] = Alw[ab + 96];
                al[2] = Alw[ab + 4];
                al[3] = Alw[ab + 100];
            }
#pragma unroll
            for (int nt = 0; nt < 4; nt++) {
                if (SPLIT == 3) {
                    MMA_BF16(acc[mt][nt], al, bhf[nt]);
                    MMA_BF16(acc[mt][nt], ah, blf[nt]);
                }
                MMA_BF16(acc[mt][nt], ah, bhf[nt]);
            }
        }
    }

    // ---- epilogue ----
    const float gm = (MODE == 2) ? *gamma : 0.0f;
#pragma unroll
    for (int mt = 0; mt < 4; mt++) {
#pragma unroll
        for (int half = 0; half < 2; half++) {
            const int m = m0 + wm + mt * 16 + gid + half * 8;
            float bvv = 0.0f;
            if (MODE == 0 || MODE == 1) bvv = bias[m];
#pragma unroll
            for (int nt = 0; nt < 4; nt++) {
                const int col = n0 + wn + nt * 8 + tig * 2;
                float v0 = acc[mt][nt][half * 2 + 0];
                float v1 = acc[mt][nt][half * 2 + 1];
                if (MODE == 0) {
                    v0 = fmaxf(v0 + bvv, 0.0f);
                    v1 = fmaxf(v1 + bvv, 0.0f);
                } else if (MODE == 1) {
                    v0 += bvv;
                    v1 += bvv;
                } else if (MODE == 2) {
                    const float* rp = resAll + (size_t)z * cStride +
                                      (size_t)m * NPIX + col;
                    v0 = fmaf(gm, v0, rp[0]);
                    v1 = fmaf(gm, v1, rp[1]);
                }
                *(float2*)(Cb + (size_t)m * NPIX + col) = make_float2(v0, v1);
            }
        }
    }

    // ---- fused per-column max over this block's BM rows (softmax axis) ----
    if (STATS) {
        float cmax[8];
#pragma unroll
        for (int j = 0; j < 8; j++) cmax[j] = -3.402823466e38f;
#pragma unroll
        for (int nt = 0; nt < 4; nt++)
#pragma unroll
            for (int c = 0; c < 2; c++)
#pragma unroll
                for (int mt = 0; mt < 4; mt++)
#pragma unroll
                    for (int half = 0; half < 2; half++)
                        cmax[nt * 2 + c] = fmaxf(cmax[nt * 2 + c],
                                                 acc[mt][nt][half * 2 + c]);
#pragma unroll
        for (int j = 0; j < 8; j++)
#pragma unroll
            for (int o = 4; o < 32; o <<= 1)
                cmax[j] = fmaxf(cmax[j], __shfl_xor_sync(0xffffffffu, cmax[j], o));
        if (lane < 4) {
#pragma unroll
            for (int nt = 0; nt < 4; nt++)
#pragma unroll
                for (int c = 0; c < 2; c++)
                    sstat[warp >> 2][wn + nt * 8 + tig * 2 + c] = cmax[nt * 2 + c];
        }
        __syncthreads();
        if (t < 128) {
            float mx = sstat[0][t];
#pragma unroll
            for (int r = 1; r < BM / 64; r++) mx = fmaxf(mx, sstat[r][t]);
            g_scratch[OFF_PM + ((size_t)z * (4096 / BM) + blockIdx.y) * NPIX +
                      n0 + t] = mx;
        }
    }
}

// ---------------------------------------------------------------------------
__global__ void comb_max()
{
    const int m = blockIdx.x * 256 + threadIdx.x;
    const int b = blockIdx.y;
    float mx = -3.402823466e38f;
    for (int s = 0; s < 16; s++)
        mx = fmaxf(mx, g_scratch[OFF_PM + ((size_t)b * 16 + s) * NPIX + m]);
    g_scratch[OFF_FM + (size_t)b * NPIX + m] = mx;
}

// in-place: attn <- exp(attn - max); per-slab sums to PS
__global__ void exp_pass(float* __restrict__ attnAll)
{
    const int m  = blockIdx.x * 256 + threadIdx.x;
    const int b  = blockIdx.z;
    const int ns = blockIdx.y;
    const float mx = g_scratch[OFF_FM + (size_t)b * NPIX + m];
    float* p = attnAll + (size_t)b * NPIX * NPIX + (size_t)ns * 128 * NPIX + m;
    float s = 0.0f;
#pragma unroll 4
    for (int n = 0; n < 128; n++) {
        float e = __expf(p[(size_t)n * NPIX] - mx);
        p[(size_t)n * NPIX] = e;
        s += e;
    }
    g_scratch[OFF_PS + ((size_t)b * 32 + ns) * NPIX + m] = s;
}

__global__ void comb_sum()
{
    const int m = blockIdx.x * 256 + threadIdx.x;
    const int b = blockIdx.y;
    float s = 0.0f;
    for (int i = 0; i < 32; i++)
        s += g_scratch[OFF_PS + ((size_t)b * 32 + i) * NPIX + m];
    g_scratch[OFF_FS + (size_t)b * NPIX + m] = 1.0f / s;
}

// ---------------------------------------------------------------------------
extern "C" void kernel_launch(void* const* d_in, const int* in_sizes, int n_in,
                              void* d_out, int out_size)
{
    (void)in_sizes; (void)n_in; (void)out_size;

    const float* x     = (const float*)d_in[0];
    const float* wf1   = (const float*)d_in[1];
    const float* bf1   = (const float*)d_in[2];
    const float* wf2   = (const float*)d_in[3];
    const float* bf2   = (const float*)d_in[4];
    const float* wg1   = (const float*)d_in[5];
    const float* bg1   = (const float*)d_in[6];
    const float* wg2   = (const float*)d_in[7];
    const float* bg2   = (const float*)d_in[8];
    const float* wh    = (const float*)d_in[9];
    const float* bh    = (const float*)d_in[10];
    const float* gamma = (const float*)d_in[11];

    float* out  = (float*)d_out;                       // (B, C, H, W)
    float* attn = out + (size_t)4 * 256 * NPIX;        // (B, N, N)

    float* scratch = nullptr;
    cudaGetSymbolAddress((void**)&scratch, g_scratch);
    float* tbuf = scratch + OFF_T;
    float* fbuf = scratch + OFF_F;
    float* gbuf = scratch + OFF_G;
    float* hbuf = scratch + OFF_H;

    const size_t sX  = (size_t)256 * NPIX;
    const size_t sCh = (size_t)128 * NPIX;
    const size_t sAt = (size_t)NPIX * NPIX;

    const int sm1_128 = (128 * 12 + 128 * 12) * 4;     // A+B hi tiles, 12 KB
    const int sm3_128 = sm1_128 * 2;                   // 24 KB
    const int sm1_256 = (256 * 12 + 128 * 12) * 4;     // 18 KB
    const int sm3_256 = sm1_256 * 2;                   // 36 KB

    // projections: f/g path bf16x3-split, h single bf16
    mma_gemm<128, 0, 3, 0, 0><<<dim3(32, 1, 4), 256, sm3_128>>>(
        wf1, 0, 256, x, sX, bf1, nullptr, nullptr, tbuf, sCh, 256, nullptr);
    mma_gemm<128, 0, 3, 1, 0><<<dim3(32, 1, 4), 256, sm3_128>>>(
        wf2, 0, 128, tbuf, sCh, bf2, nullptr, nullptr, fbuf, sCh, 128, nullptr);
    mma_gemm<128, 0, 3, 0, 0><<<dim3(32, 1, 4), 256, sm3_128>>>(
        wg1, 0, 256, x, sX, bg1, nullptr, nullptr, tbuf, sCh, 256, nullptr);
    mma_gemm<128, 0, 3, 1, 0><<<dim3(32, 1, 4), 256, sm3_128>>>(
        wg2, 0, 128, tbuf, sCh, bg2, nullptr, nullptr, gbuf, sCh, 128, nullptr);
    mma_gemm<256, 0, 1, 1, 0><<<dim3(32, 1, 4), 512, sm1_256>>>(
        wh, 0, 256, x, sX, bh, nullptr, nullptr, hbuf, sX, 256, nullptr);

    // attn logits = f^T g (bf16x3) -> d_out attn region + fused col-max
    mma_gemm<256, 1, 3, 3, 1><<<dim3(32, 16, 4), 512, sm3_256>>>(
        fbuf, sCh, NPIX, gbuf, sCh, nullptr, nullptr, nullptr,
        attn, sAt, 128, nullptr);

    comb_max<<<dim3(16, 4), 256>>>();
    exp_pass<<<dim3(16, 32, 4), 256>>>(attn);
    comb_sum<<<dim3(16, 4), 256>>>();

    // final: out = gamma*(h @ attn_soft) + x; B staging scales e by inv[col]
    // and writes normalized attn back in-place (sole-reader blocks -> no race)
    mma_gemm<256, 0, 1, 2, 0><<<dim3(32, 1, 4), 512, sm1_256>>>(
        hbuf, sX, NPIX, attn, sAt, nullptr, x, gamma, out, sX, 4096, attn);
}

// round 11
// speedup vs baseline: 1.5902x; 1.2334x over previous
#include <cuda_runtime.h>
#include <cuda_bf16.h>
#include <cstdint>

// Problem-fixed shapes: B=4, C=256, Ch=128, H=W=64 -> N=4096
#define NPIX 4096

// ---------------- scratch (no allocations allowed -> __device__ global) ----
#define OFF_T  0
#define OFF_F  2097152
#define OFF_G  4194304
#define OFF_H  6291456
#define OFF_PM 10485760
#define OFF_PS 11010048
#define OFF_FM 11534336
#define OFF_FS 11550720
#define OFF_T2 11567104
#define SCRATCH_FLOATS (11567104 + 2097152)

static __device__ float g_scratch[SCRATCH_FLOATS];

// ---------------------------------------------------------------------------
__device__ __forceinline__ unsigned packbf(float x, float y) {
    __nv_bfloat162 t = __floats2bfloat162_rn(x, y);   // .x = low half
    return reinterpret_cast<unsigned&>(t);
}
__device__ __forceinline__ float bfhi(float x) {
    return __bfloat162float(__float2bfloat16(x));
}
__device__ __forceinline__ void ldsm4(unsigned& r0, unsigned& r1,
                                      unsigned& r2, unsigned& r3, unsigned a) {
    asm volatile("ldmatrix.sync.aligned.m8n8.x4.shared.b16 {%0,%1,%2,%3}, [%4];"
                 : "=r"(r0), "=r"(r1), "=r"(r2), "=r"(r3) : "r"(a));
}

#define MMA_BF16(c, a, b)                                                    \
    asm volatile(                                                            \
        "mma.sync.aligned.m16n8k16.row.col.f32.bf16.bf16.f32 "               \
        "{%0,%1,%2,%3},{%4,%5,%6,%7},{%8,%9},{%0,%1,%2,%3};"                 \
        : "+f"(c[0]), "+f"(c[1]), "+f"(c[2]), "+f"(c[3])                     \
        : "r"(a[0]), "r"(a[1]), "r"(a[2]), "r"(a[3]), "r"(b[0]), "r"(b[1]))

// ---------------------------------------------------------------------------
// bf16 tensor-core GEMM:  C[M x 4096] = epi( A[M x K] @ X[K x 4096] )
//   BM 128 (256 thr) / 256 (512 thr); tile BM x 128, BK=16.
//   ACM=1: A stored k-major (f for attn gemm).
//   SPLIT=3: bf16 hi/lo 3-product compensation. SPLIT=1: single bf16.
//   MODE 0: relu(acc+bias)  1: acc+bias
//        2: final (B scaled by inv[col] at staging + normalized writeback
//           to eWr; out = gamma*acc + res)
//        3: store exp(acc)  (attn logits -> e, no max shift needed)
//   STATS=1: per-(slab,col) SUM of stored C values -> PS (softmax denom).
//   DUAL=1: blockIdx.y selects {A,bias,X,C} vs {A2,bias2,X2,C2}, m0=0.
// Smem: bf16 pairs as u32 words; row pitch 12 words -> conflict-free LDSM.
// ---------------------------------------------------------------------------
template <int BM, int ACM, int SPLIT, int MODE, int STATS, int DUAL>
__global__ __launch_bounds__(BM * 2)
void mma_gemm(const float* __restrict__ A, const float* __restrict__ A2,
              size_t aStride, int lda,
              const float* __restrict__ X, const float* __restrict__ X2,
              size_t xStride,
              const float* __restrict__ bias, const float* __restrict__ bias2,
              const float* __restrict__ resAll,
              const float* __restrict__ gamma,
              float* __restrict__ C, float* __restrict__ C2,
              size_t cStride, int K,
              float* __restrict__ eWr)
{
    constexpr int AW = BM * 12;      // A tile words
    constexpr int BW = 128 * 12;     // B tile words
    constexpr int KPT = 1024 / BM;   // B k-rows per thread (8 or 4)

    extern __shared__ unsigned smw[];
    unsigned* Ahw = smw;
    unsigned* Bhw = smw + AW;
    unsigned* Alw = (SPLIT == 3) ? (smw + AW + BW) : smw;
    unsigned* Blw = (SPLIT == 3) ? (smw + AW + BW + AW) : smw;

    __shared__ float sstat[4][128];

    const int z = blockIdx.z;
    const float* Asel = A;
    const float* Xsel = X;
    const float* bsel = bias;
    float*       Csel = C;
    if (DUAL && blockIdx.y == 1) { Asel = A2; Xsel = X2; bsel = bias2; Csel = C2; }

    const float* Ab = Asel + (size_t)z * aStride;
    const float* Xb = Xsel + (size_t)z * xStride;
    float*       Cb = Csel + (size_t)z * cStride;
    float*       eWrB = (MODE == 2) ? (eWr + (size_t)z * xStride) : (float*)nullptr;

    const int m0   = DUAL ? 0 : blockIdx.y * BM;
    const int n0   = blockIdx.x * 128;
    const int t    = threadIdx.x;
    const int lane = t & 31;
    const int warp = t >> 5;
    const int wm   = (warp >> 2) * 64;
    const int wn   = (warp & 3) * 32;
    const int tig  = lane & 3;

    // staging maps
    const int nB   = t & 127;
    const int kbB  = (t >> 7) * KPT;
    const int mA0  = t >> 1;              // ACM0
    const int kshA = (t & 1) * 8;
    const int mA1  = t & (BM - 1);        // ACM1
    const int kbA  = (t >= BM) ? 8 : 0;

    // ldmatrix addresses (constant across k-tiles; single-buffered smem)
    const unsigned AhB = (unsigned)__cvta_generic_to_shared(Ahw);
    const unsigned AlB = (unsigned)__cvta_generic_to_shared(Alw);
    const unsigned BhB = (unsigned)__cvta_generic_to_shared(Bhw);
    const unsigned BlB = (unsigned)__cvta_generic_to_shared(Blw);
    const int aRow = ((lane >> 3) & 1) * 8 + (lane & 7);
    const int aKh  = (lane >> 4) * 4;
    const int bRow = (lane >> 4) * 8 + (lane & 7);
    const int bKh  = ((lane >> 3) & 1) * 4;
    unsigned aAH[4], aAL[4], bAH[2], bAL[2];
#pragma unroll
    for (int mt = 0; mt < 4; mt++) {
        const unsigned w = (unsigned)((wm + mt * 16 + aRow) * 12 + aKh) * 4u;
        aAH[mt] = AhB + w;
        aAL[mt] = AlB + w;
    }
#pragma unroll
    for (int p = 0; p < 2; p++) {
        const unsigned w = (unsigned)((wn + p * 16 + bRow) * 12 + bKh) * 4u;
        bAH[p] = BhB + w;
        bAL[p] = BlB + w;
    }

    const float inv_n = (MODE == 2)
        ? g_scratch[OFF_FS + (size_t)z * NPIX + n0 + nB] : 0.0f;

    float acc[4][4][4];
#pragma unroll
    for (int mt = 0; mt < 4; mt++)
#pragma unroll
        for (int nt = 0; nt < 4; nt++)
#pragma unroll
            for (int r = 0; r < 4; r++) acc[mt][nt][r] = 0.0f;

    float  bv[KPT];
    float  av[8];
    float4 a4[2];

    auto loadStage = [&](int k0) {
#pragma unroll
        for (int j = 0; j < KPT; j++) {
            const size_t gi = (size_t)(k0 + kbB + j) * NPIX + n0 + nB;
            float v = Xb[gi];
            if (MODE == 2) { v *= inv_n; eWrB[gi] = v; }
            bv[j] = v;
        }
        if (ACM) {
#pragma unroll
            for (int j = 0; j < 8; j++)
                av[j] = Ab[(size_t)(k0 + kbA + j) * lda + m0 + mA1];
        } else {
            a4[0] = *(const float4*)(Ab + (size_t)(m0 + mA0) * lda + k0 + kshA);
            a4[1] = *(const float4*)(Ab + (size_t)(m0 + mA0) * lda + k0 + kshA + 4);
        }
    };

    auto storeStage = [&]() {
#pragma unroll
        for (int j2 = 0; j2 < KPT / 2; j2++) {
            const float x0 = bv[2 * j2], x1 = bv[2 * j2 + 1];
            const int w = nB * 12 + kbB / 2 + j2;
            Bhw[w] = packbf(x0, x1);
            if (SPLIT == 3) Blw[w] = packbf(x0 - bfhi(x0), x1 - bfhi(x1));
        }
        if (ACM) {
#pragma unroll
            for (int j2 = 0; j2 < 4; j2++) {
                const float x0 = av[2 * j2], x1 = av[2 * j2 + 1];
                const int w = mA1 * 12 + kbA / 2 + j2;
                Ahw[w] = packbf(x0, x1);
                if (SPLIT == 3) Alw[w] = packbf(x0 - bfhi(x0), x1 - bfhi(x1));
            }
        } else {
            const int w = mA0 * 12 + kshA / 2;
            const float xs[8] = {a4[0].x, a4[0].y, a4[0].z, a4[0].w,
                                 a4[1].x, a4[1].y, a4[1].z, a4[1].w};
#pragma unroll
            for (int j2 = 0; j2 < 4; j2++) {
                const float x0 = xs[2 * j2], x1 = xs[2 * j2 + 1];
                Ahw[w + j2] = packbf(x0, x1);
                if (SPLIT == 3) Alw[w + j2] = packbf(x0 - bfhi(x0), x1 - bfhi(x1));
            }
        }
    };

    loadStage(0);

    for (int k0 = 0; k0 < K; k0 += 16) {
        __syncthreads();
        storeStage();
        if (k0 + 16 < K) loadStage(k0 + 16);
        __syncthreads();

        unsigned bhf[4][2], blf[4][2];
#pragma unroll
        for (int p = 0; p < 2; p++) {
            ldsm4(bhf[2 * p][0], bhf[2 * p][1],
                  bhf[2 * p + 1][0], bhf[2 * p + 1][1], bAH[p]);
            if (SPLIT == 3)
                ldsm4(blf[2 * p][0], blf[2 * p][1],
                      blf[2 * p + 1][0], blf[2 * p + 1][1], bAL[p]);
        }
#pragma unroll
        for (int mt = 0; mt < 4; mt++) {
            unsigned ah[4], al[4];
            ldsm4(ah[0], ah[1], ah[2], ah[3], aAH[mt]);
            if (SPLIT == 3) ldsm4(al[0], al[1], al[2], al[3], aAL[mt]);
#pragma unroll
            for (int nt = 0; nt < 4; nt++) {
                if (SPLIT == 3) {
                    MMA_BF16(acc[mt][nt], al, bhf[nt]);
                    MMA_BF16(acc[mt][nt], ah, blf[nt]);
                }
                MMA_BF16(acc[mt][nt], ah, bhf[nt]);
            }
        }
    }

    // ---- epilogue (+ optional exp and column-sum stats) ----
    const float gm = (MODE == 2) ? *gamma : 0.0f;
    const int gid = lane >> 2;
    float colsum[8];
    if (STATS) {
#pragma unroll
        for (int j = 0; j < 8; j++) colsum[j] = 0.0f;
    }
#pragma unroll
    for (int mt = 0; mt < 4; mt++) {
#pragma unroll
        for (int half = 0; half < 2; half++) {
            const int m = m0 + wm + mt * 16 + gid + half * 8;
            float bvv = 0.0f;
            if (MODE == 0 || MODE == 1) bvv = bsel[m];
#pragma unroll
            for (int nt = 0; nt < 4; nt++) {
                const int col = n0 + wn + nt * 8 + tig * 2;
                float v0 = acc[mt][nt][half * 2 + 0];
                float v1 = acc[mt][nt][half * 2 + 1];
                if (MODE == 0) {
                    v0 = fmaxf(v0 + bvv, 0.0f);
                    v1 = fmaxf(v1 + bvv, 0.0f);
                } else if (MODE == 1) {
                    v0 += bvv;
                    v1 += bvv;
                } else if (MODE == 2) {
                    const float* rp = resAll + (size_t)z * cStride +
                                      (size_t)m * NPIX + col;
                    v0 = fmaf(gm, v0, rp[0]);
                    v1 = fmaf(gm, v1, rp[1]);
                } else if (MODE == 3) {
                    v0 = __expf(v0);
                    v1 = __expf(v1);
                }
                if (STATS) {
                    colsum[nt * 2 + 0] += v0;
                    colsum[nt * 2 + 1] += v1;
                }
                *(float2*)(Cb + (size_t)m * NPIX + col) = make_float2(v0, v1);
            }
        }
    }

    if (STATS) {
        // sum over the warp's 64 rows: xor offsets 4/8/16 vary gid, keep tig
#pragma unroll
        for (int j = 0; j < 8; j++)
#pragma unroll
            for (int o = 4; o < 32; o <<= 1)
                colsum[j] += __shfl_xor_sync(0xffffffffu, colsum[j], o);
        if (lane < 4) {
#pragma unroll
            for (int nt = 0; nt < 4; nt++)
#pragma unroll
                for (int c = 0; c < 2; c++)
                    sstat[warp >> 2][wn + nt * 8 + tig * 2 + c] = colsum[nt * 2 + c];
        }
        __syncthreads();
        if (t < 128) {
            float s = sstat[0][t];
#pragma unroll
            for (int r = 1; r < BM / 64; r++) s += sstat[r][t];
            g_scratch[OFF_PS + ((size_t)z * (4096 / BM) + blockIdx.y) * NPIX +
                      n0 + t] = s;
        }
    }
}

// ---------------------------------------------------------------------------
__global__ void comb_sum()
{
    const int m = blockIdx.x * 256 + threadIdx.x;
    const int b = blockIdx.y;
    float s = 0.0f;
    for (int i = 0; i < 16; i++)
        s += g_scratch[OFF_PS + ((size_t)b * 16 + i) * NPIX + m];
    g_scratch[OFF_FS + (size_t)b * NPIX + m] = 1.0f / s;
}

// ---------------------------------------------------------------------------
extern "C" void kernel_launch(void* const* d_in, const int* in_sizes, int n_in,
                              void* d_out, int out_size)
{
    (void)in_sizes; (void)n_in; (void)out_size;

    const float* x     = (const float*)d_in[0];
    const float* wf1   = (const float*)d_in[1];
    const float* bf1   = (const float*)d_in[2];
    const float* wf2   = (const float*)d_in[3];
    const float* bf2   = (const float*)d_in[4];
    const float* wg1   = (const float*)d_in[5];
    const float* bg1   = (const float*)d_in[6];
    const float* wg2   = (const float*)d_in[7];
    const float* bg2   = (const float*)d_in[8];
    const float* wh    = (const float*)d_in[9];
    const float* bh    = (const float*)d_in[10];
    const float* gamma = (const float*)d_in[11];

    float* out  = (float*)d_out;                       // (B, C, H, W)
    float* attn = out + (size_t)4 * 256 * NPIX;        // (B, N, N)

    float* scratch = nullptr;
    cudaGetSymbolAddress((void**)&scratch, g_scratch);
    float* tbuf  = scratch + OFF_T;
    float* t2buf = scratch + OFF_T2;
    float* fbuf  = scratch + OFF_F;
    float* gbuf  = scratch + OFF_G;
    float* hbuf  = scratch + OFF_H;

    const size_t sX  = (size_t)256 * NPIX;
    const size_t sCh = (size_t)128 * NPIX;
    const size_t sAt = (size_t)NPIX * NPIX;

    const int sm1_128 = (128 * 12 + 128 * 12) * 4;     // 12 KB
    const int sm3_128 = sm1_128 * 2;                   // 24 KB
    const int sm1_256 = (256 * 12 + 128 * 12) * 4;     // 18 KB
    const int sm3_256 = sm1_256 * 2;                   // 36 KB

    // f1+g1 (dual), then f2+g2 (dual): bf16x3-split
    mma_gemm<128, 0, 3, 0, 0, 1><<<dim3(32, 2, 4), 256, sm3_128>>>(
        wf1, wg1, 0, 256, x, x, sX, bf1, bg1, nullptr, nullptr,
        tbuf, t2buf, sCh, 256, nullptr);
    mma_gemm<128, 0, 3, 1, 0, 1><<<dim3(32, 2, 4), 256, sm3_128>>>(
        wf2, wg2, 0, 128, tbuf, t2buf, sCh, bf2, bg2, nullptr, nullptr,
        fbuf, gbuf, sCh, 128, nullptr);

    // h projection (single bf16)
    mma_gemm<256, 0, 1, 1, 0, 0><<<dim3(32, 1, 4), 512, sm1_256>>>(
        wh, nullptr, 0, 256, x, nullptr, sX, bh, nullptr, nullptr, nullptr,
        hbuf, nullptr, sX, 256, nullptr);

    // attn: e = exp(f^T g) (bf16x3) -> d_out attn region + fused column sums
    mma_gemm<256, 1, 3, 3, 1, 0><<<dim3(32, 16, 4), 512, sm3_256>>>(
        fbuf, nullptr, sCh, NPIX, gbuf, nullptr, sCh, nullptr, nullptr,
        nullptr, nullptr, attn, nullptr, sAt, 128, nullptr);

    comb_sum<<<dim3(16, 4), 256>>>();

    // final: out = gamma*(h @ attn_soft) + x; B staging scales e by inv[col]
    // and writes normalized attn back in-place (sole-reader blocks, no race)
    mma_gemm<256, 0, 1, 2, 0, 0><<<dim3(32, 1, 4), 512, sm1_256>>>(
        hbuf, nullptr, sX, NPIX, attn, nullptr, sAt, nullptr, nullptr,
        x, gamma, out, nullptr, sX, 4096, attn);
}

// round 12
// speedup vs baseline: 1.6492x; 1.0371x over previous
#include <cuda_runtime.h>
#include <cuda_bf16.h>
#include <cstdint>

// Problem-fixed shapes: B=4, C=256, Ch=128, H=W=64 -> N=4096
#define NPIX 4096

// ---------------- scratch (no allocations allowed -> __device__ global) ----
// F region: packed f (hi plane then lo plane), each 4*4096*64 u32 words
// G region: packed g likewise.  T/T2: f1/g1 fp32 temps.  H: h fp32.
#define OFF_T  0
#define OFF_F  2097152
#define OFF_G  4194304
#define OFF_H  6291456
#define OFF_PM 10485760
#define OFF_PS 11010048
#define OFF_FM 11534336
#define OFF_FS 11550720
#define OFF_T2 11567104
#define SCRATCH_FLOATS (11567104 + 2097152)

static __device__ float g_scratch[SCRATCH_FLOATS];

#define PK_BATCH 262144   // 4096*64 words per batch per plane
#define PK_PLANE 1048576  // 4 batches

// ---------------------------------------------------------------------------
__device__ __forceinline__ unsigned packbf(float x, float y) {
    __nv_bfloat162 t = __floats2bfloat162_rn(x, y);   // .x = low half
    return reinterpret_cast<unsigned&>(t);
}
__device__ __forceinline__ float bfhi(float x) {
    return __bfloat162float(__float2bfloat16(x));
}
__device__ __forceinline__ void ldsm4(unsigned& r0, unsigned& r1,
                                      unsigned& r2, unsigned& r3, unsigned a) {
    asm volatile("ldmatrix.sync.aligned.m8n8.x4.shared.b16 {%0,%1,%2,%3}, [%4];"
                 : "=r"(r0), "=r"(r1), "=r"(r2), "=r"(r3) : "r"(a));
}
__device__ __forceinline__ void cp16(unsigned dst, const void* src) {
    asm volatile("cp.async.cg.shared.global [%0], [%1], 16;"
                 :: "r"(dst), "l"(src));
}

#define MMA_BF16(c, a, b)                                                    \
    asm volatile(                                                            \
        "mma.sync.aligned.m16n8k16.row.col.f32.bf16.bf16.f32 "               \
        "{%0,%1,%2,%3},{%4,%5,%6,%7},{%8,%9},{%0,%1,%2,%3};"                 \
        : "+f"(c[0]), "+f"(c[1]), "+f"(c[2]), "+f"(c[3])                     \
        : "r"(a[0]), "r"(a[1]), "r"(a[2]), "r"(a[3]), "r"(b[0]), "r"(b[1]))

// ---------------------------------------------------------------------------
// Generic bf16 tensor-core GEMM (projections + final), as in R10 but with
// MODE 4: bias-add then write packed bf16 hi/lo pair-words (f2/g2 -> attn
// operand layout [n][c/2]); no fp32 C store in that mode.
// ---------------------------------------------------------------------------
template <int BM, int ACM, int SPLIT, int MODE, int DUAL>
__global__ __launch_bounds__(BM * 2)
void mma_gemm(const float* __restrict__ A, const float* __restrict__ A2,
              size_t aStride, int lda,
              const float* __restrict__ X, const float* __restrict__ X2,
              size_t xStride,
              const float* __restrict__ bias, const float* __restrict__ bias2,
              const float* __restrict__ resAll,
              const float* __restrict__ gamma,
              float* __restrict__ C, float* __restrict__ C2,
              size_t cStride, int K,
              float* __restrict__ eWr,
              unsigned* __restrict__ Pkh, unsigned* __restrict__ Pkh2,
              unsigned* __restrict__ Pkl, unsigned* __restrict__ Pkl2)
{
    constexpr int AW = BM * 12;
    constexpr int BW = 128 * 12;
    constexpr int KPT = 1024 / BM;

    extern __shared__ unsigned smw[];
    unsigned* Ahw = smw;
    unsigned* Bhw = smw + AW;
    unsigned* Alw = (SPLIT == 3) ? (smw + AW + BW) : smw;
    unsigned* Blw = (SPLIT == 3) ? (smw + AW + BW + AW) : smw;

    const int z = blockIdx.z;
    const float* Asel = A;
    const float* Xsel = X;
    const float* bsel = bias;
    float*       Csel = C;
    unsigned*    PhSel = Pkh;
    unsigned*    PlSel = Pkl;
    if (DUAL && blockIdx.y == 1) {
        Asel = A2; Xsel = X2; bsel = bias2; Csel = C2; PhSel = Pkh2; PlSel = Pkl2;
    }

    const float* Ab = Asel + (size_t)z * aStride;
    const float* Xb = Xsel + (size_t)z * xStride;
    float*       Cb = Csel ? Csel + (size_t)z * cStride : (float*)nullptr;
    float*       eWrB = (MODE == 2) ? (eWr + (size_t)z * xStride) : (float*)nullptr;
    unsigned*    PhB = (MODE == 4) ? PhSel + (size_t)z * PK_BATCH : (unsigned*)nullptr;
    unsigned*    PlB = (MODE == 4) ? PlSel + (size_t)z * PK_BATCH : (unsigned*)nullptr;

    const int m0   = DUAL ? 0 : blockIdx.y * BM;
    const int n0   = blockIdx.x * 128;
    const int t    = threadIdx.x;
    const int lane = t & 31;
    const int warp = t >> 5;
    const int wm   = (warp >> 2) * 64;
    const int wn   = (warp & 3) * 32;
    const int tig  = lane & 3;

    const int nB   = t & 127;
    const int kbB  = (t >> 7) * KPT;
    const int mA0  = t >> 1;
    const int kshA = (t & 1) * 8;
    const int mA1  = t & (BM - 1);
    const int kbA  = (t >= BM) ? 8 : 0;

    const unsigned AhB = (unsigned)__cvta_generic_to_shared(Ahw);
    const unsigned AlB = (unsigned)__cvta_generic_to_shared(Alw);
    const unsigned BhB = (unsigned)__cvta_generic_to_shared(Bhw);
    const unsigned BlB = (unsigned)__cvta_generic_to_shared(Blw);
    const int aRow = ((lane >> 3) & 1) * 8 + (lane & 7);
    const int aKh  = (lane >> 4) * 4;
    const int bRow = (lane >> 4) * 8 + (lane & 7);
    const int bKh  = ((lane >> 3) & 1) * 4;
    unsigned aAH[4], aAL[4], bAH[2], bAL[2];
#pragma unroll
    for (int mt = 0; mt < 4; mt++) {
        const unsigned w = (unsigned)((wm + mt * 16 + aRow) * 12 + aKh) * 4u;
        aAH[mt] = AhB + w;
        aAL[mt] = AlB + w;
    }
#pragma unroll
    for (int p = 0; p < 2; p++) {
        const unsigned w = (unsigned)((wn + p * 16 + bRow) * 12 + bKh) * 4u;
        bAH[p] = BhB + w;
        bAL[p] = BlB + w;
    }

    const float inv_n = (MODE == 2)
        ? g_scratch[OFF_FS + (size_t)z * NPIX + n0 + nB] : 0.0f;

    float acc[4][4][4];
#pragma unroll
    for (int mt = 0; mt < 4; mt++)
#pragma unroll
        for (int nt = 0; nt < 4; nt++)
#pragma unroll
            for (int r = 0; r < 4; r++) acc[mt][nt][r] = 0.0f;

    float  bv[KPT];
    float  av[8];
    float4 a4[2];

    auto loadStage = [&](int k0) {
#pragma unroll
        for (int j = 0; j < KPT; j++) {
            const size_t gi = (size_t)(k0 + kbB + j) * NPIX + n0 + nB;
            float v = Xb[gi];
            if (MODE == 2) { v *= inv_n; eWrB[gi] = v; }
            bv[j] = v;
        }
        if (ACM) {
#pragma unroll
            for (int j = 0; j < 8; j++)
                av[j] = Ab[(size_t)(k0 + kbA + j) * lda + m0 + mA1];
        } else {
            a4[0] = *(const float4*)(Ab + (size_t)(m0 + mA0) * lda + k0 + kshA);
            a4[1] = *(const float4*)(Ab + (size_t)(m0 + mA0) * lda + k0 + kshA + 4);
        }
    };

    auto storeStage = [&]() {
#pragma unroll
        for (int j2 = 0; j2 < KPT / 2; j2++) {
            const float x0 = bv[2 * j2], x1 = bv[2 * j2 + 1];
            const int w = nB * 12 + kbB / 2 + j2;
            Bhw[w] = packbf(x0, x1);
            if (SPLIT == 3) Blw[w] = packbf(x0 - bfhi(x0), x1 - bfhi(x1));
        }
        if (ACM) {
#pragma unroll
            for (int j2 = 0; j2 < 4; j2++) {
                const float x0 = av[2 * j2], x1 = av[2 * j2 + 1];
                const int w = mA1 * 12 + kbA / 2 + j2;
                Ahw[w] = packbf(x0, x1);
                if (SPLIT == 3) Alw[w] = packbf(x0 - bfhi(x0), x1 - bfhi(x1));
            }
        } else {
            const int w = mA0 * 12 + kshA / 2;
            const float xs[8] = {a4[0].x, a4[0].y, a4[0].z, a4[0].w,
                                 a4[1].x, a4[1].y, a4[1].z, a4[1].w};
#pragma unroll
            for (int j2 = 0; j2 < 4; j2++) {
                const float x0 = xs[2 * j2], x1 = xs[2 * j2 + 1];
                Ahw[w + j2] = packbf(x0, x1);
                if (SPLIT == 3) Alw[w + j2] = packbf(x0 - bfhi(x0), x1 - bfhi(x1));
            }
        }
    };

    loadStage(0);

    for (int k0 = 0; k0 < K; k0 += 16) {
        __syncthreads();
        storeStage();
        if (k0 + 16 < K) loadStage(k0 + 16);
        __syncthreads();

        unsigned bhf[4][2], blf[4][2];
#pragma unroll
        for (int p = 0; p < 2; p++) {
            ldsm4(bhf[2 * p][0], bhf[2 * p][1],
                  bhf[2 * p + 1][0], bhf[2 * p + 1][1], bAH[p]);
            if (SPLIT == 3)
                ldsm4(blf[2 * p][0], blf[2 * p][1],
                      blf[2 * p + 1][0], blf[2 * p + 1][1], bAL[p]);
        }
#pragma unroll
        for (int mt = 0; mt < 4; mt++) {
            unsigned ah[4], al[4];
            ldsm4(ah[0], ah[1], ah[2], ah[3], aAH[mt]);
            if (SPLIT == 3) ldsm4(al[0], al[1], al[2], al[3], aAL[mt]);
#pragma unroll
            for (int nt = 0; nt < 4; nt++) {
                if (SPLIT == 3) {
                    MMA_BF16(acc[mt][nt], al, bhf[nt]);
                    MMA_BF16(acc[mt][nt], ah, blf[nt]);
                }
                MMA_BF16(acc[mt][nt], ah, bhf[nt]);
            }
        }
    }

    // ---- epilogue ----
    const float gm = (MODE == 2) ? *gamma : 0.0f;
    const int gid = lane >> 2;
#pragma unroll
    for (int mt = 0; mt < 4; mt++) {
#pragma unroll
        for (int half = 0; half < 2; half++) {
            const int m = m0 + wm + mt * 16 + gid + half * 8;
            float bvv = 0.0f;
            if (MODE == 0 || MODE == 1 || MODE == 4) bvv = bsel[m];
#pragma unroll
            for (int nt = 0; nt < 4; nt++) {
                const int col = n0 + wn + nt * 8 + tig * 2;
                float v0 = acc[mt][nt][half * 2 + 0];
                float v1 = acc[mt][nt][half * 2 + 1];
                if (MODE == 0) {
                    v0 = fmaxf(v0 + bvv, 0.0f);
                    v1 = fmaxf(v1 + bvv, 0.0f);
                } else if (MODE == 1 || MODE == 4) {
                    v0 += bvv;
                    v1 += bvv;
                } else if (MODE == 2) {
                    const float* rp = resAll + (size_t)z * cStride +
                                      (size_t)m * NPIX + col;
                    v0 = fmaf(gm, v0, rp[0]);
                    v1 = fmaf(gm, v1, rp[1]);
                }
                if (MODE == 4) {
                    // pair channel rows (m even) with (m+1): partner in lane+4
                    const float p0 = __shfl_down_sync(0xffffffffu, v0, 4);
                    const float p1 = __shfl_down_sync(0xffffffffu, v1, 4);
                    if ((gid & 1) == 0) {
                        const size_t w0 = (size_t)col * 64 + (m >> 1);
                        PhB[w0]      = packbf(v0, p0);
                        PlB[w0]      = packbf(v0 - bfhi(v0), p0 - bfhi(p0));
                        PhB[w0 + 64] = packbf(v1, p1);
                        PlB[w0 + 64] = packbf(v1 - bfhi(v1), p1 - bfhi(p1));
                    }
                } else {
                    *(float2*)(Cb + (size_t)m * NPIX + col) = make_float2(v0, v1);
                }
            }
        }
    }
}

// ---------------------------------------------------------------------------
// Dedicated attn kernel: e = exp(f^T g) with bf16 hi/lo 3-product MMA.
// Operands pre-packed ([row][c/2] pair-words); cp.async double-buffered.
// Output: fp32 e -> attn region; per-(slab,col) sums -> PS.
// grid (32 m-tiles, 16 n-tiles, 4 batch), 512 threads.
// ---------------------------------------------------------------------------
__global__ __launch_bounds__(512)
void attn_gemm(const unsigned* __restrict__ fh, const unsigned* __restrict__ fl,
               const unsigned* __restrict__ gh, const unsigned* __restrict__ gl,
               float* __restrict__ attnAll)
{
    constexpr int AS = 256 * 12;          // A plane words per stage
    constexpr int BS = 128 * 12;          // B plane words per stage
    constexpr int STW = 2 * AS + 2 * BS;  // stage words (Ah, Al, Bh, Bl)

    extern __shared__ unsigned smw[];
    __shared__ float sstat[4][128];

    const int z = blockIdx.z;
    const unsigned* fhB = fh + (size_t)z * PK_BATCH;
    const unsigned* flB = fl + (size_t)z * PK_BATCH;
    const unsigned* ghB = gh + (size_t)z * PK_BATCH;
    const unsigned* glB = gl + (size_t)z * PK_BATCH;
    float* Cb = attnAll + (size_t)z * (size_t)NPIX * NPIX;

    const int n0 = blockIdx.y * 256;      // attn rows (softmax axis)
    const int c0 = blockIdx.x * 128;      // attn cols
    const int t    = threadIdx.x;
    const int lane = t & 31;
    const int warp = t >> 5;
    const int wm   = (warp >> 2) * 64;
    const int wn   = (warp & 3) * 32;
    const int gid  = lane >> 2;
    const int tig  = lane & 3;

    // cp.async maps
    const int arow = t >> 1, achk = (t & 1) * 4;
    const int brow = (t & 255) >> 1, bchk = (t & 1) * 4, bbuf = t >> 8;
    const unsigned smB = (unsigned)__cvta_generic_to_shared(smw);
    const unsigned dA  = smB + (unsigned)(arow * 12 + achk) * 4u;
    const unsigned dB  = smB + (unsigned)(2 * AS + bbuf * BS +
                                          brow * 12 + bchk) * 4u;
    const unsigned* bSrc = bbuf ? glB : ghB;

    auto issue = [&](int tile, int stage) {
        const unsigned so = (unsigned)(stage * STW) * 4u;
        const int kw = tile * 8;
        cp16(dA + so,            fhB + (size_t)(n0 + arow) * 64 + kw + achk);
        cp16(dA + AS * 4u + so,  flB + (size_t)(n0 + arow) * 64 + kw + achk);
        cp16(dB + so,            bSrc + (size_t)(c0 + brow) * 64 + kw + bchk);
        asm volatile("cp.async.commit_group;");
    };

    // ldmatrix addresses (stage 0)
    const int aRow = ((lane >> 3) & 1) * 8 + (lane & 7);
    const int aKh  = (lane >> 4) * 4;
    const int bRow = (lane >> 4) * 8 + (lane & 7);
    const int bKh  = ((lane >> 3) & 1) * 4;
    unsigned aAH[4], aAL[4], bAH[2], bAL[2];
#pragma unroll
    for (int mt = 0; mt < 4; mt++) {
        const unsigned w = (unsigned)((wm + mt * 16 + aRow) * 12 + aKh) * 4u;
        aAH[mt] = smB + w;
        aAL[mt] = smB + AS * 4u + w;
    }
#pragma unroll
    for (int p = 0; p < 2; p++) {
        const unsigned w = (unsigned)((wn + p * 16 + bRow) * 12 + bKh) * 4u;
        bAH[p] = smB + 2u * AS * 4u + w;
        bAL[p] = smB + (2u * AS + BS) * 4u + w;
    }

    float acc[4][4][4];
#pragma unroll
    for (int mt = 0; mt < 4; mt++)
#pragma unroll
        for (int nt = 0; nt < 4; nt++)
#pragma unroll
            for (int r = 0; r < 4; r++) acc[mt][nt][r] = 0.0f;

    issue(0, 0);
    issue(1, 1);

#pragma unroll
    for (int tile = 0; tile < 8; tile++) {
        const int stage = tile & 1;
        if (tile == 7) asm volatile("cp.async.wait_group 0;");
        else           asm volatile("cp.async.wait_group 1;");
        __syncthreads();

        const unsigned so = (unsigned)(stage * STW) * 4u;
        unsigned bhf[4][2], blf[4][2];
#pragma unroll
        for (int p = 0; p < 2; p++) {
            ldsm4(bhf[2 * p][0], bhf[2 * p][1],
                  bhf[2 * p + 1][0], bhf[2 * p + 1][1], bAH[p] + so);
            ldsm4(blf[2 * p][0], blf[2 * p][1],
                  blf[2 * p + 1][0], blf[2 * p + 1][1], bAL[p] + so);
        }
#pragma unroll
        for (int mt = 0; mt < 4; mt++) {
            unsigned ah[4], al[4];
            ldsm4(ah[0], ah[1], ah[2], ah[3], aAH[mt] + so);
            ldsm4(al[0], al[1], al[2], al[3], aAL[mt] + so);
#pragma unroll
            for (int nt = 0; nt < 4; nt++) {
                MMA_BF16(acc[mt][nt], al, bhf[nt]);
                MMA_BF16(acc[mt][nt], ah, blf[nt]);
                MMA_BF16(acc[mt][nt], ah, bhf[nt]);
            }
        }
        __syncthreads();
        if (tile + 2 < 8) issue(tile + 2, stage);
    }

    // ---- epilogue: e = exp(acc), store + column sums ----
    float colsum[8];
#pragma unroll
    for (int j = 0; j < 8; j++) colsum[j] = 0.0f;
#pragma unroll
    for (int mt = 0; mt < 4; mt++) {
#pragma unroll
        for (int half = 0; half < 2; half++) {
            const int m = n0 + wm + mt * 16 + gid + half * 8;
#pragma unroll
            for (int nt = 0; nt < 4; nt++) {
                const int col = c0 + wn + nt * 8 + tig * 2;
                const float v0 = __expf(acc[mt][nt][half * 2 + 0]);
                const float v1 = __expf(acc[mt][nt][half * 2 + 1]);
                colsum[nt * 2 + 0] += v0;
                colsum[nt * 2 + 1] += v1;
                *(float2*)(Cb + (size_t)m * NPIX + col) = make_float2(v0, v1);
            }
        }
    }
#pragma unroll
    for (int j = 0; j < 8; j++)
#pragma unroll
        for (int o = 4; o < 32; o <<= 1)
            colsum[j] += __shfl_xor_sync(0xffffffffu, colsum[j], o);
    if (lane < 4) {
#pragma unroll
        for (int nt = 0; nt < 4; nt++)
#pragma unroll
            for (int c = 0; c < 2; c++)
                sstat[warp >> 2][wn + nt * 8 + tig * 2 + c] = colsum[nt * 2 + c];
    }
    __syncthreads();
    if (t < 128) {
        float s = sstat[0][t];
#pragma unroll
        for (int r = 1; r < 4; r++) s += sstat[r][t];
        g_scratch[OFF_PS + ((size_t)z * 16 + blockIdx.y) * NPIX + c0 + t] = s;
    }
}

// ---------------------------------------------------------------------------
__global__ void comb_sum()
{
    const int m = blockIdx.x * 256 + threadIdx.x;
    const int b = blockIdx.y;
    float s = 0.0f;
    for (int i = 0; i < 16; i++)
        s += g_scratch[OFF_PS + ((size_t)b * 16 + i) * NPIX + m];
    g_scratch[OFF_FS + (size_t)b * NPIX + m] = 1.0f / s;
}

// ---------------------------------------------------------------------------
extern "C" void kernel_launch(void* const* d_in, const int* in_sizes, int n_in,
                              void* d_out, int out_size)
{
    (void)in_sizes; (void)n_in; (void)out_size;

    const float* x     = (const float*)d_in[0];
    const float* wf1   = (const float*)d_in[1];
    const float* bf1   = (const float*)d_in[2];
    const float* wf2   = (const float*)d_in[3];
    const float* bf2   = (const float*)d_in[4];
    const float* wg1   = (const float*)d_in[5];
    const float* bg1   = (const float*)d_in[6];
    const float* wg2   = (const float*)d_in[7];
    const float* bg2   = (const float*)d_in[8];
    const float* wh    = (const float*)d_in[9];
    const float* bh    = (const float*)d_in[10];
    const float* gamma = (const float*)d_in[11];

    float* out  = (float*)d_out;                       // (B, C, H, W)
    float* attn = out + (size_t)4 * 256 * NPIX;        // (B, N, N)

    float* scratch = nullptr;
    cudaGetSymbolAddress((void**)&scratch, g_scratch);
    float* tbuf  = scratch + OFF_T;
    float* t2buf = scratch + OFF_T2;
    float* hbuf  = scratch + OFF_H;
    unsigned* fh = (unsigned*)(scratch + OFF_F);
    unsigned* fl = fh + PK_PLANE;
    unsigned* gh = (unsigned*)(scratch + OFF_G);
    unsigned* gl = gh + PK_PLANE;

    const size_t sX  = (size_t)256 * NPIX;
    const size_t sCh = (size_t)128 * NPIX;
    const size_t sAt = (size_t)NPIX * NPIX;

    const int sm1_128 = (128 * 12 + 128 * 12) * 4;     // 12 KB
    const int sm3_128 = sm1_128 * 2;                   // 24 KB
    const int sm1_256 = (256 * 12 + 128 * 12) * 4;     // 18 KB
    const int smAttn  = 2 * (2 * 256 * 12 + 2 * 128 * 12) * 4;  // 72 KB

    static int smemSet = 0;
    if (!smemSet) {
        cudaFuncSetAttribute(attn_gemm,
                             cudaFuncAttributeMaxDynamicSharedMemorySize, smAttn);
        smemSet = 1;
    }

    // f1+g1 (dual, relu, 3-split) -> fp32 temps
    mma_gemm<128, 0, 3, 0, 1><<<dim3(32, 2, 4), 256, sm3_128>>>(
        wf1, wg1, 0, 256, x, x, sX, bf1, bg1, nullptr, nullptr,
        tbuf, t2buf, sCh, 256, nullptr, nullptr, nullptr, nullptr, nullptr);

    // f2+g2 (dual, 3-split) -> packed bf16 hi/lo attn operands
    mma_gemm<128, 0, 3, 4, 1><<<dim3(32, 2, 4), 256, sm3_128>>>(
        wf2, wg2, 0, 128, tbuf, t2buf, sCh, bf2, bg2, nullptr, nullptr,
        nullptr, nullptr, 0, 128, nullptr, fh, gh, fl, gl);

    // h projection (single bf16) -> fp32 h
    mma_gemm<256, 0, 1, 1, 0><<<dim3(32, 1, 4), 512, sm1_256>>>(
        wh, nullptr, 0, 256, x, nullptr, sX, bh, nullptr, nullptr, nullptr,
        hbuf, nullptr, sX, 256, nullptr, nullptr, nullptr, nullptr, nullptr);

    // attn: e = exp(f^T g) -> d_out attn region + fused column sums
    attn_gemm<<<dim3(32, 16, 4), 512, smAttn>>>(fh, fl, gh, gl, attn);

    comb_sum<<<dim3(16, 4), 256>>>();

    // final: out = gamma*(h @ attn_soft) + x; B staging scales e by inv[col]
    // and writes normalized attn back in-place (sole-reader blocks, no race)
    mma_gemm<256, 0, 1, 2, 0><<<dim3(32, 1, 4), 512, sm1_256>>>(
        hbuf, nullptr, sX, NPIX, attn, nullptr, sAt, nullptr, nullptr,
        x, gamma, out, nullptr, sX, 4096, attn,
        nullptr, nullptr, nullptr, nullptr);
}